// round 16
// baseline (speedup 1.0000x reference)
#include <cuda_runtime.h>
#include <cstdint>

// Cost volume: out[b,k,h,w] = (1/81) * sum_c x1[b,c,h,w] * x2[b,c,h-i,w-j]
//   i,j in [-4,4], k = (9i+j) mod 81. Zero padding. B=4,C=128,H=128,W=256,D=81.
//
// R15: 18 warps/SM via HALVED TILE. RF accounting: acc pool per tile =
// px*81 floats regardless of decomposition; 2h x 64w tile -> 10368 floats ->
// 36 acc/thread at 288 threads (9 warps, warp g owns di=g-4, P=4 px/lane).
// Live set ~90 regs fits the lb(288,2) cap of 113 WITHOUT spills (unlike R3's
// 4h tile, which needed 72 acc + window and blew the same cap). 2 CTAs/SM =
// 18 warps: FFMA demand 2.25/cyc/SM-pipe > rt=2 supply -> pipe saturates.
// Single-barrier cp.async double buffer, CC=4, as in R9 (92.3us best).

#define Bn 4
#define Cn 128
#define Hn 128
#define Wn 256
#define Dn 81
#define TH 2
#define TW 64
#define CC 4
#define NCH (Cn / CC)       // 32 chunks
#define S2H (TH + 8)        // 10
#define S2W (TW + 8)        // 72
#define NTHR 288

#define S1_F4 (CC * TH * TW / 4)    // 128
#define S2_F4 (CC * S2H * S2W / 4)  // 720

__device__ __forceinline__ void cp16(uint32_t saddr, const float* gptr, bool ok) {
    int sz = ok ? 16 : 0;
    asm volatile("cp.async.cg.shared.global [%0], [%1], 16, %2;\n"
                 :: "r"(saddr), "l"(gptr), "r"(sz));
}
__device__ __forceinline__ void cp_commit() {
    asm volatile("cp.async.commit_group;\n" ::: "memory");
}
template <int N>
__device__ __forceinline__ void cp_wait() {
    asm volatile("cp.async.wait_group %0;\n" :: "n"(N) : "memory");
}

__global__ __launch_bounds__(NTHR, 2)
void costvol_kernel(const float* __restrict__ x1,
                    const float* __restrict__ x2,
                    float* __restrict__ out) {
    __shared__ __align__(16) float s1[2][CC][TH][TW];   // 2 * 2 KB
    __shared__ __align__(16) float s2[2][CC][S2H][S2W]; // 2 * 11.25 KB

    const int w0 = blockIdx.x * TW;
    const int h0 = blockIdx.y * TH;
    const int b  = blockIdx.z;

    const int tid  = threadIdx.x;
    const int g    = tid >> 5;       // warp id = ii (di = g-4), 0..8
    const int lane = tid & 31;
    const int ty   = lane >> 4;      // 2 rows
    const int tx   = lane & 15;      // 16 pixel-quads across w (P=4)

    const float* x1b = x1 + (size_t)(b * Cn) * Hn * Wn;
    const float* x2b = x2 + (size_t)(b * Cn) * Hn * Wn;

    auto prefetch = [&](int c0, int st) {
        // s1: 128 float4 (threads 0..127)
        if (tid < S1_F4) {
            int cc  = tid >> 5;               // 32 f4 per channel
            int rem = tid & 31;
            int hh  = rem >> 4;               // 16 f4 per row
            int k4  = rem & 15;
            uint32_t sa = (uint32_t)__cvta_generic_to_shared(&s1[st][cc][hh][4 * k4]);
            cp16(sa, x1b + (((size_t)(c0 + cc) * Hn + h0 + hh) * Wn + w0 + 4 * k4), true);
        }
        // s2: 720 float4 (3 rounds of 288, last partial)
#pragma unroll
        for (int q = 0; q < 3; q++) {
            int f = tid + q * NTHR;
            if (f < S2_F4) {
                int cc  = f / (S2H * (S2W / 4));          // /180
                int rem = f - cc * (S2H * (S2W / 4));
                int row = rem / (S2W / 4);                // /18
                int k4  = rem - row * (S2W / 4);
                int hg  = h0 - 4 + row;
                int wg  = w0 - 4 + 4 * k4;
                bool ok = ((unsigned)hg < (unsigned)Hn) && ((unsigned)wg < (unsigned)Wn);
                const float* gp = ok ? (x2b + (((size_t)cc + c0) * Hn + hg) * (size_t)Wn + wg)
                                     : x2b;
                uint32_t sa = (uint32_t)__cvta_generic_to_shared(&s2[st][cc][row][4 * k4]);
                cp16(sa, gp, ok);
            }
        }
        cp_commit();
    };

    float acc[9][4];
#pragma unroll
    for (int jj = 0; jj < 9; jj++)
#pragma unroll
        for (int p = 0; p < 4; p++) acc[jj][p] = 0.f;

    prefetch(0, 0);

    for (int it = 0; it < NCH; it++) {
        const int st = it & 1;
        cp_wait<0>();
        // Single barrier: publishes chunk `it` AND proves all readers of
        // stage st^1 are done, so the refill below is race-free.
        __syncthreads();
        if (it + 1 < NCH) prefetch((it + 1) * CC, st ^ 1);

#pragma unroll
        for (int cc = 0; cc < CC; cc++) {
            const float4 av = *(const float4*)&s1[st][cc][ty][4 * tx];
            const float a[4] = {av.x, av.y, av.z, av.w};
            // x2 window: 12 floats, row ty+8-g (in [ty, ty+8] + halo), col 4*tx
            const float* rp = &s2[st][cc][ty + 8 - g][4 * tx];
            float wnd[12];
#pragma unroll
            for (int m = 0; m < 12; m += 4) {
                float4 t = *(const float4*)(rp + m);   // aligned LDS.128
                wnd[m] = t.x; wnd[m + 1] = t.y; wnd[m + 2] = t.z; wnd[m + 3] = t.w;
            }
#pragma unroll
            for (int jj = 0; jj < 9; jj++) {
#pragma unroll
                for (int p = 0; p < 4; p++)
                    acc[jj][p] += a[p] * wnd[p + 8 - jj];
            }
        }
    }

    // ---- epilogue: ii = g, k = (9*g + jj + 41) mod 81 ----
    const float inv = 1.0f / 81.0f;
    const int hg = h0 + ty;
    const int wg = w0 + 4 * tx;
#pragma unroll
    for (int jj = 0; jj < 9; jj++) {
        int k = 9 * g + jj + 41;
        if (k >= 81) k -= 81;
        float4 v = make_float4(acc[jj][0] * inv, acc[jj][1] * inv,
                               acc[jj][2] * inv, acc[jj][3] * inv);
        *(float4*)(out + (((size_t)((b * Dn + k) * Hn + hg)) * Wn + wg)) = v;
    }
}

extern "C" void kernel_launch(void* const* d_in, const int* in_sizes, int n_in,
                              void* d_out, int out_size) {
    (void)in_sizes; (void)n_in; (void)out_size;
    const float* x1 = (const float*)d_in[0];
    const float* x2 = (const float*)d_in[1];
    float* out = (float*)d_out;
    dim3 grid(Wn / TW, Hn / TH, Bn);   // (4, 64, 4) = 1024 blocks
    costvol_kernel<<<grid, NTHR>>>(x1, x2, out);
}

// round 17
// speedup vs baseline: 1.1640x; 1.1640x over previous
#include <cuda_runtime.h>
#include <cstdint>

// Cost volume: out[b,k,h,w] = (1/81) * sum_c x1[b,c,h,w] * x2[b,c,h-i,w-j]
//   i,j in [-4,4], k = (9i+j) mod 81. Zero padding. B=4,C=128,H=128,W=256,D=81.
//
// R16 = R9 (best: 92.3us) with the prefetch ADDRESS ARITHMETIC HOISTED out of
// the chunk loop. R9 re-derived all 7 cp.async slot addresses every chunk
// (~60-70 alu ops/thread/chunk = ~38% of issue slots are non-FFMA). All of it
// is chunk-invariant except the channel offset -> precompute slots once, per
// chunk just issue cp16(saddr + st*STAGE, gptr, ok) and gptr += CC*H*W.
// Compute loop / geometry / single-barrier cp.async pipeline unchanged:
// 192 thr = 3 groups x 64, group g owns di in {3g..3g+2}; 4h x 64w tile,
// P=4 px/thread; CC=4; launch_bounds(192,2).

#define Bn 4
#define Cn 128
#define Hn 128
#define Wn 256
#define Dn 81
#define TH 4
#define TW 64
#define CC 4
#define NCH (Cn / CC)       // 32 chunks
#define S2H (TH + 8)        // 12
#define S2W (TW + 8)        // 72
#define NTHR 192

#define S1_F4 (CC * TH * TW / 4)    // 256
#define S2_F4 (CC * S2H * S2W / 4)  // 864
#define S1_STAGE_BYTES (CC * TH * TW * 4)    // 4096
#define S2_STAGE_BYTES (CC * S2H * S2W * 4)  // 13824
#define CH_STRIDE ((size_t)CC * Hn * Wn)     // floats per chunk step

__device__ __forceinline__ void cp16(uint32_t saddr, const float* gptr, bool ok) {
    int sz = ok ? 16 : 0;
    asm volatile("cp.async.cg.shared.global [%0], [%1], 16, %2;\n"
                 :: "r"(saddr), "l"(gptr), "r"(sz));
}
__device__ __forceinline__ void cp_commit() {
    asm volatile("cp.async.commit_group;\n" ::: "memory");
}
template <int N>
__device__ __forceinline__ void cp_wait() {
    asm volatile("cp.async.wait_group %0;\n" :: "n"(N) : "memory");
}

__global__ __launch_bounds__(NTHR, 2)
void costvol_kernel(const float* __restrict__ x1,
                    const float* __restrict__ x2,
                    float* __restrict__ out) {
    __shared__ __align__(16) float s1[2][CC][TH][TW];   // 2 * 4 KB
    __shared__ __align__(16) float s2[2][CC][S2H][S2W]; // 2 * 13.5 KB

    const int w0 = blockIdx.x * TW;
    const int h0 = blockIdx.y * TH;
    const int b  = blockIdx.z;

    const int tid = threadIdx.x;
    const int g   = tid / 64;        // i-group 0..2
    const int r   = tid - g * 64;
    const int tx  = r & 15;          // 16 pixel-quads across w
    const int ty  = r >> 4;          // 4 rows

    const float* x1b = x1 + (size_t)(b * Cn) * Hn * Wn;
    const float* x2b = x2 + (size_t)(b * Cn) * Hn * Wn;

    // ---- ONE-TIME precomputation of all prefetch slots (chunk-invariant) ----
    const float* g1[2]; uint32_t a1[2]; bool v1[2];
#pragma unroll
    for (int q = 0; q < 2; q++) {
        int f = tid + q * NTHR;
        v1[q] = (f < S1_F4);
        int fc = v1[q] ? f : 0;
        int cc  = fc >> 6;
        int rem = fc & 63;
        int hh  = rem >> 4;
        int k4  = rem & 15;
        g1[q] = x1b + (((size_t)cc * Hn + h0 + hh) * Wn + w0 + 4 * k4);
        a1[q] = (uint32_t)__cvta_generic_to_shared(&s1[0][cc][hh][4 * k4]);
    }
    const float* g2[5]; uint32_t a2[5]; bool v2[5]; bool ok2[5];
#pragma unroll
    for (int q = 0; q < 5; q++) {
        int f = tid + q * NTHR;
        v2[q] = (f < S2_F4);
        int fc = v2[q] ? f : 0;
        int cc  = fc / (S2H * (S2W / 4));
        int rem = fc - cc * (S2H * (S2W / 4));
        int row = rem / (S2W / 4);
        int k4  = rem - row * (S2W / 4);
        int hg  = h0 - 4 + row;
        int wg  = w0 - 4 + 4 * k4;
        ok2[q] = ((unsigned)hg < (unsigned)Hn) && ((unsigned)wg < (unsigned)Wn);
        g2[q] = ok2[q] ? (x2b + ((size_t)cc * Hn + hg) * (size_t)Wn + wg) : x2b;
        a2[q] = (uint32_t)__cvta_generic_to_shared(&s2[0][cc][row][4 * k4]);
    }

    // Issue prefetch for current stage, then advance pointers by one chunk.
    auto issue = [&](int st) {
#pragma unroll
        for (int q = 0; q < 2; q++)
            if (v1[q]) { cp16(a1[q] + st * S1_STAGE_BYTES, g1[q], true); g1[q] += CH_STRIDE; }
#pragma unroll
        for (int q = 0; q < 5; q++)
            if (v2[q]) { cp16(a2[q] + st * S2_STAGE_BYTES, g2[q], ok2[q]); g2[q] += CH_STRIDE; }
        cp_commit();
    };

    float acc[3][9][4];
#pragma unroll
    for (int u = 0; u < 3; u++)
#pragma unroll
        for (int jj = 0; jj < 9; jj++)
#pragma unroll
            for (int p = 0; p < 4; p++) acc[u][jj][p] = 0.f;

    issue(0);   // chunk 0 -> stage 0

    for (int it = 0; it < NCH; it++) {
        const int st = it & 1;
        cp_wait<0>();
        // Single barrier: publishes chunk `it` AND proves all readers of
        // stage st^1 are done, so the refill below is race-free.
        __syncthreads();
        if (it + 1 < NCH) issue(st ^ 1);

#pragma unroll
        for (int cc = 0; cc < CC; cc++) {
            const float4 av = *(const float4*)&s1[st][cc][ty][4 * tx];
            const float a[4] = {av.x, av.y, av.z, av.w};
#pragma unroll
            for (int u = 0; u < 3; u++) {
                const float* rp = &s2[st][cc][ty + 8 - 3 * g - u][4 * tx];
                float wnd[12];
#pragma unroll
                for (int m = 0; m < 12; m += 4) {
                    float4 t = *(const float4*)(rp + m);   // aligned LDS.128
                    wnd[m] = t.x; wnd[m + 1] = t.y; wnd[m + 2] = t.z; wnd[m + 3] = t.w;
                }
#pragma unroll
                for (int jj = 0; jj < 9; jj++) {
#pragma unroll
                    for (int p = 0; p < 4; p++)
                        acc[u][jj][p] += a[p] * wnd[p + 8 - jj];
                }
            }
        }
    }

    // ---- epilogue: k = (9*ii + jj + 41) mod 81, ii = 3g+u ----
    const float inv = 1.0f / 81.0f;
    const int hg = h0 + ty;
    const int wg = w0 + 4 * tx;
#pragma unroll
    for (int u = 0; u < 3; u++) {
        const int ii = 3 * g + u;
#pragma unroll
        for (int jj = 0; jj < 9; jj++) {
            int k = 9 * ii + jj + 41;
            if (k >= 81) k -= 81;
            float4 v = make_float4(acc[u][jj][0] * inv, acc[u][jj][1] * inv,
                                   acc[u][jj][2] * inv, acc[u][jj][3] * inv);
            *(float4*)(out + (((size_t)((b * Dn + k) * Hn + hg)) * Wn + wg)) = v;
        }
    }
}

extern "C" void kernel_launch(void* const* d_in, const int* in_sizes, int n_in,
                              void* d_out, int out_size) {
    (void)in_sizes; (void)n_in; (void)out_size;
    const float* x1 = (const float*)d_in[0];
    const float* x2 = (const float*)d_in[1];
    float* out = (float*)d_out;
    dim3 grid(Wn / TW, Hn / TH, Bn);   // (4, 32, 4) = 512 blocks
    costvol_kernel<<<grid, NTHR>>>(x1, x2, out);
}